// round 3
// baseline (speedup 1.0000x reference)
#include <cuda_runtime.h>
#include <cstdint>
#include <math.h>

// ===== Problem dims =====
#define BB   16384     // batch
#define K1   784       // input features
#define HH   1024      // hidden
#define NW   32        // HH/32 words per packed row
#define NOUT 10
#define NPART 128      // partial-reduction blocks
#define RPB  (BB/NPART)   // 128 rows per stats block

// ===== Scratch (device globals; no allocation allowed) =====
__device__ float    g_h[(size_t)BB*HH];     // 64 MiB preactivation buffer (reused per layer)
__device__ unsigned g_nv[BB*NW];            // packed noisy-binarized bits
__device__ unsigned g_act[BB*NW];           // packed activations (input to next GEMM)
__device__ float    g_sW1[K1*HH];           // sign(W1)^T as floats, [k][n]
__device__ unsigned g_w2[HH*NW];            // packed sign(W2), [n][word]
__device__ unsigned g_w3[HH*NW];
__device__ unsigned g_w4[NOUT*NW];
__device__ double   g_part[NPART][2*HH];    // fixed-order reduction partials (sum, sumsq)
__device__ float    g_muf[HH];
__device__ float    g_rf[HH];               // invstd = rsqrt(var+eps)
__device__ unsigned g_sel[NW];              // BN-LUT: out = (nv & sel) ^ mb
__device__ unsigned g_mb[NW];

// ===================================================================
// Prep: sign(W1)^T as floats (handles sign(0)=0 exactly)
// ===================================================================
__global__ void k_signW1(const float* __restrict__ W1) {
    int idx = blockIdx.x * 256 + threadIdx.x;      // K1*HH = 802816 = 3136*256
    int k = idx / HH, n = idx % HH;
    float w = W1[(size_t)n * K1 + k];
    g_sW1[idx] = (w > 0.f) ? 1.f : ((w < 0.f) ? -1.f : 0.f);
}

// Pack sign bits of a weight matrix (bit=1 <=> weight>0 <=> +1)
__global__ void k_packW(const float* __restrict__ W, int which, int total) {
    int idx = blockIdx.x * 256 + threadIdx.x;
    unsigned* dst = (which == 0) ? g_w2 : (which == 1) ? g_w3 : g_w4;
    bool pos = (idx < total) ? (W[idx] > 0.f) : false;
    unsigned bal = __ballot_sync(0xffffffffu, pos);
    if ((threadIdx.x & 31) == 0 && idx < total) dst[idx >> 5] = bal;
}

// ===================================================================
// Layer 1: fp32 SGEMM  h1[B,HH] = X[B,K1] * sW1[K1,HH]
// 128x128 tile, BK=16, 256 threads, 8x8 per thread. 784 = 49*16 exact.
// ===================================================================
__global__ __launch_bounds__(256) void k_gemm1(const float* __restrict__ X) {
    __shared__ float As[16][128];   // [k][m]
    __shared__ float Bs[16][128];   // [k][n]
    int bn0 = blockIdx.x * 128;
    int bm0 = blockIdx.y * 128;
    int tid = threadIdx.x;
    int ty = tid >> 4, tx = tid & 15;

    float acc[8][8];
#pragma unroll
    for (int i = 0; i < 8; i++)
#pragma unroll
        for (int j = 0; j < 8; j++) acc[i][j] = 0.f;

    for (int kt = 0; kt < K1; kt += 16) {
#pragma unroll
        for (int i = 0; i < 2; i++) {
            int p = tid * 2 + i;                    // 0..511
            int ar = p >> 2, ac = (p & 3) << 2;     // A: 128 rows x 16 cols
            float4 av = *(const float4*)&X[(size_t)(bm0 + ar) * K1 + kt + ac];
            As[ac + 0][ar] = av.x; As[ac + 1][ar] = av.y;
            As[ac + 2][ar] = av.z; As[ac + 3][ar] = av.w;
            int br = p >> 5, bc = (p & 31) << 2;    // B: 16 rows x 128 cols
            float4 bv = *(const float4*)&g_sW1[(size_t)(kt + br) * HH + bn0 + bc];
            *(float4*)&Bs[br][bc] = bv;
        }
        __syncthreads();
#pragma unroll
        for (int k = 0; k < 16; k++) {
            float a[8], b[8];
#pragma unroll
            for (int i = 0; i < 8; i++) a[i] = As[k][ty * 8 + i];
#pragma unroll
            for (int j = 0; j < 8; j++) b[j] = Bs[k][tx * 8 + j];
#pragma unroll
            for (int i = 0; i < 8; i++)
#pragma unroll
                for (int j = 0; j < 8; j++) acc[i][j] += a[i] * b[j];
        }
        __syncthreads();
    }
#pragma unroll
    for (int i = 0; i < 8; i++) {
        float* p = &g_h[(size_t)(bm0 + ty * 8 + i) * HH + bn0 + tx * 8];
        *(float4*)p       = make_float4(acc[i][0], acc[i][1], acc[i][2], acc[i][3]);
        *(float4*)(p + 4) = make_float4(acc[i][4], acc[i][5], acc[i][6], acc[i][7]);
    }
}

// ===================================================================
// BN1 stats: per-block column sums/sumsq (double), fixed-order
// ===================================================================
__global__ __launch_bounds__(256) void k_stats1() {
    int blk = blockIdx.x;            // 0..127
    int r0 = blk * RPB;
    int t = threadIdx.x;
    double s[4] = {0, 0, 0, 0}, sq[4] = {0, 0, 0, 0};
    for (int r = 0; r < RPB; r++) {
        const float* row = &g_h[(size_t)(r0 + r) * HH];
#pragma unroll
        for (int q = 0; q < 4; q++) {
            float v = row[t + 256 * q];
            s[q] += (double)v;
            sq[q] += (double)v * (double)v;
        }
    }
#pragma unroll
    for (int q = 0; q < 4; q++) {
        g_part[blk][t + 256 * q]      = s[q];
        g_part[blk][HH + t + 256 * q] = sq[q];
    }
}

__global__ void k_reduce1() {
    int c = blockIdx.x * 256 + threadIdx.x;   // 4 blocks * 256 = 1024
    double s = 0, sq = 0;
    for (int p = 0; p < NPART; p++) { s += g_part[p][c]; sq += g_part[p][HH + c]; }
    double mu = s / (double)BB;
    double var = sq / (double)BB - mu * mu;
    g_muf[c] = (float)mu;
    g_rf[c]  = (float)(1.0 / sqrt(var + 1e-5));
}

// Pack sign(batchnorm(h1)) into g_act. One thread per element, warp-ballot per word.
__global__ void k_pack1(const float* __restrict__ gv, const float* __restrict__ bv) {
    int idx = blockIdx.x * 256 + threadIdx.x;     // BB*HH = 65536*256
    int c = idx & (HH - 1);
    float h = g_h[idx];
    // match jax's unfused (h-mu)*rsqrt*g + b ordering
    float z = __fadd_rn(__fmul_rn(__fmul_rn(__fsub_rn(h, g_muf[c]), g_rf[c]), gv[c]), bv[c]);
    unsigned bal = __ballot_sync(0xffffffffu, z > 0.f);
    if ((threadIdx.x & 31) == 0) g_act[idx >> 5] = bal;
}

// ===================================================================
// Binary GEMM (layers 2,3): g_h[b,n] = 1024 - 2*sum_w popc(act ^ w)
// 128x128 tile, full K (32 words) in smem, 8x8 per thread. Bit-exact.
// ===================================================================
__global__ __launch_bounds__(256) void k_bgemm(int which) {
    __shared__ unsigned As[32][128];   // [word][m]
    __shared__ unsigned Ws[32][128];   // [word][n]
    const unsigned* __restrict__ Wb = (which == 0) ? g_w2 : g_w3;
    int bn0 = blockIdx.x * 128;
    int bm0 = blockIdx.y * 128;
    int tid = threadIdx.x;
    int ty = tid >> 4, tx = tid & 15;

#pragma unroll
    for (int i = 0; i < 4; i++) {
        int p = tid * 4 + i;                 // 0..1023
        int r = p >> 3, c4 = (p & 7) << 2;   // 128 rows x 32 words, uint4
        uint4 av = *(const uint4*)&g_act[(size_t)(bm0 + r) * NW + c4];
        As[c4 + 0][r] = av.x; As[c4 + 1][r] = av.y;
        As[c4 + 2][r] = av.z; As[c4 + 3][r] = av.w;
        uint4 wv = *(const uint4*)&Wb[(size_t)(bn0 + r) * NW + c4];
        Ws[c4 + 0][r] = wv.x; Ws[c4 + 1][r] = wv.y;
        Ws[c4 + 2][r] = wv.z; Ws[c4 + 3][r] = wv.w;
    }
    __syncthreads();

    int acc[8][8];
#pragma unroll
    for (int i = 0; i < 8; i++)
#pragma unroll
        for (int j = 0; j < 8; j++) acc[i][j] = 0;

    for (int w = 0; w < 32; w++) {
        unsigned a[8], b[8];
#pragma unroll
        for (int i = 0; i < 8; i++) a[i] = As[w][ty * 8 + i];
#pragma unroll
        for (int j = 0; j < 8; j++) b[j] = Ws[w][tx * 8 + j];
#pragma unroll
        for (int i = 0; i < 8; i++)
#pragma unroll
            for (int j = 0; j < 8; j++) acc[i][j] += __popc(a[i] ^ b[j]);
    }
#pragma unroll
    for (int i = 0; i < 8; i++) {
        float* p = &g_h[(size_t)(bm0 + ty * 8 + i) * HH + bn0 + tx * 8];
        *(float4*)p = make_float4((float)(HH - 2 * acc[i][0]), (float)(HH - 2 * acc[i][1]),
                                  (float)(HH - 2 * acc[i][2]), (float)(HH - 2 * acc[i][3]));
        *(float4*)(p + 4) = make_float4((float)(HH - 2 * acc[i][4]), (float)(HH - 2 * acc[i][5]),
                                        (float)(HH - 2 * acc[i][6]), (float)(HH - 2 * acc[i][7]));
    }
}

// ===================================================================
// noisy_binarize + pack bits + per-block column sums of the +-1 values
// ===================================================================
__global__ __launch_bounds__(256) void k_noisy(const float* __restrict__ U) {
    int blk = blockIdx.x;       // 0..127
    int r0 = blk * RPB;
    int t = threadIdx.x;
    int lane = t & 31;
    int isum[4] = {0, 0, 0, 0};
    for (int r = 0; r < RPB; r++) {
        size_t base = (size_t)(r0 + r) * HH;
#pragma unroll
        for (int q = 0; q < 4; q++) {
            int c = t + 256 * q;
            float x = g_h[base + c];
            float uu = U[base + c];
            float s = (x > 0.f) ? 1.f : -1.f;
            float q2 = (x * x) / 50.0f;                  // fp32 division, as jax does
            double prob = 0.5 * exp(-(double)q2);        // near-correctly-rounded
            bool flip = ((double)uu < prob) && (fabsf(x) <= 50.f);
            float nv = flip ? -s : s;
            bool pos = (nv > 0.f);
            isum[q] += pos ? 1 : -1;
            unsigned bal = __ballot_sync(0xffffffffu, pos);
            if (lane == 0) g_nv[(base + c) >> 5] = bal;
        }
    }
#pragma unroll
    for (int q = 0; q < 4; q++) g_part[blk][t + 256 * q] = (double)isum[q];
}

// Reduce column sums of +-1 values; build per-column BN+sign LUT masks.
// For v in {+1,-1}: out = sign((v-mu)*rsqrt(1-mu^2+eps)*g + b); encoded as
// out_bit = (nv_bit & sel) ^ mb.
__global__ void k_lut(const float* __restrict__ gv, const float* __restrict__ bv) {
    int c = threadIdx.x;        // 1024 threads, one block
    double s = 0;
    for (int p = 0; p < NPART; p++) s += g_part[p][c];
    double mu = s / (double)BB;
    double r = 1.0 / sqrt(1.0 - mu * mu + 1e-5);
    double zp = (( 1.0 - mu) * r) * (double)gv[c] + (double)bv[c];
    double zm = ((-1.0 - mu) * r) * (double)gv[c] + (double)bv[c];
    unsigned pb = __ballot_sync(0xffffffffu, zp > 0.0);
    unsigned mb = __ballot_sync(0xffffffffu, zm > 0.0);
    if ((c & 31) == 0) {
        g_sel[c >> 5] = pb ^ mb;
        g_mb[c >> 5]  = mb;
    }
}

__global__ void k_apply() {
    int i = blockIdx.x * 256 + threadIdx.x;   // BB*NW = 2048*256
    int w = i & (NW - 1);
    g_act[i] = (g_nv[i] & g_sel[w]) ^ g_mb[w];
}

// ===================================================================
// Output layer: out[b,o] = 1024 - 2*sum_w popc(act ^ w4[o])
// ===================================================================
__global__ __launch_bounds__(256) void k_out(float* __restrict__ outp) {
    __shared__ unsigned As[256][33];          // padded: conflict-free column reads
    __shared__ unsigned W4s[NOUT][NW];
    int r0 = blockIdx.x * 256;
    int t = threadIdx.x;
#pragma unroll
    for (int i = 0; i < 32; i++) {
        int p = t + 256 * i;                  // 0..8191, linear coalesced
        As[p >> 5][p & 31] = g_act[(size_t)r0 * NW + p];
    }
    // FIX (R2 bug): NOUT*NW = 320 > blockDim(256); strided load so classes 8,9
    // get real weights instead of uninitialized smem (caused rel_err = sqrt(4/10)).
    for (int i = t; i < NOUT * NW; i += 256) ((unsigned*)W4s)[i] = g_w4[i];
    __syncthreads();
#pragma unroll
    for (int o = 0; o < NOUT; o++) {
        int cnt = 0;
#pragma unroll
        for (int w = 0; w < NW; w++) cnt += __popc(As[t][w] ^ W4s[o][w]);
        outp[(size_t)(r0 + t) * NOUT + o] = (float)(HH - 2 * cnt);
    }
}

// ===================================================================
// Launch: deterministic, graph-capturable, no allocations, no syncs.
// Input order: x, u2, u3, W1, W2, W3, W4, g1, b1, g2, b2, g3, b3
// ===================================================================
extern "C" void kernel_launch(void* const* d_in, const int* in_sizes, int n_in,
                              void* d_out, int out_size) {
    const float* x  = (const float*)d_in[0];
    const float* u2 = (const float*)d_in[1];
    const float* u3 = (const float*)d_in[2];
    const float* W1 = (const float*)d_in[3];
    const float* W2 = (const float*)d_in[4];
    const float* W3 = (const float*)d_in[5];
    const float* W4 = (const float*)d_in[6];
    const float* g1 = (const float*)d_in[7];
    const float* b1 = (const float*)d_in[8];
    const float* g2 = (const float*)d_in[9];
    const float* b2 = (const float*)d_in[10];
    const float* g3 = (const float*)d_in[11];
    const float* b3 = (const float*)d_in[12];
    float* out = (float*)d_out;

    // Prep: weight signs / packs (recomputed every call; deterministic)
    k_signW1<<<(K1 * HH) / 256, 256>>>(W1);
    k_packW<<<(HH * HH) / 256, 256>>>(W2, 0, HH * HH);
    k_packW<<<(HH * HH) / 256, 256>>>(W3, 1, HH * HH);
    k_packW<<<(NOUT * HH + 255) / 256, 256>>>(W4, 2, NOUT * HH);

    dim3 ggrid(HH / 128, BB / 128);   // (8, 128)

    // Layer 1
    k_gemm1<<<ggrid, 256>>>(x);
    k_stats1<<<NPART, 256>>>();
    k_reduce1<<<HH / 256, 256>>>();
    k_pack1<<<(BB * HH) / 256, 256>>>(g1, b1);

    // Layer 2
    k_bgemm<<<ggrid, 256>>>(0);
    k_noisy<<<NPART, 256>>>(u2);
    k_lut<<<1, HH>>>(g2, b2);
    k_apply<<<(BB * NW) / 256, 256>>>();

    // Layer 3
    k_bgemm<<<ggrid, 256>>>(1);
    k_noisy<<<NPART, 256>>>(u3);
    k_lut<<<1, HH>>>(g3, b3);
    k_apply<<<(BB * NW) / 256, 256>>>();

    // Output layer
    k_out<<<BB / 256, 256>>>(out);
}

// round 4
// speedup vs baseline: 1.1334x; 1.1334x over previous
#include <cuda_runtime.h>
#include <cstdint>
#include <math.h>

// ===== Problem dims =====
#define BB   16384     // batch
#define K1   784       // input features
#define HH   1024      // hidden
#define NW   32        // HH/32 words per packed row
#define NOUT 10
#define NPART 128      // partial-reduction blocks
#define RPB  (BB/NPART)   // 128 rows per stats block

// ===== Scratch (device globals; no allocation allowed) =====
__device__ float    g_h[(size_t)BB*HH];     // 64 MiB preactivation buffer (reused per layer)
__device__ unsigned g_nv[BB*NW];            // packed noisy-binarized bits
__device__ unsigned g_act[BB*NW];           // packed activations (input to next GEMM)
__device__ float    g_sW1[K1*HH];           // sign(W1)^T as floats, [k][n]
__device__ unsigned g_w2[HH*NW];            // packed sign(W2), [n][word]
__device__ unsigned g_w3[HH*NW];
__device__ unsigned g_w4[NOUT*NW];
__device__ double   g_part[NPART][2*HH];    // fixed-order reduction partials
__device__ float    g_muf[HH];
__device__ float    g_rf[HH];               // invstd = rsqrt(var+eps)
__device__ unsigned g_sel[NW];              // BN-LUT: out = (nv & sel) ^ mb
__device__ unsigned g_mb[NW];
__device__ float    g_lutf[27];             // fp32 flip thresholds, indexed by min(|x|/2, 26)

// ===================================================================
// Flip-probability LUT. x = 2m (even integer). For m <= 25 (|x| <= 50):
//   prob = 0.5*exp(-(double)((x*x)/50.0f))   [identical ops to the R3 path]
// Store t = smallest fp32 >= prob, so that for fp32 u:
//   (u < t)  <=>  ((double)u < prob)   EXACTLY.
// m >= 26: never flips -> t = -1 (u >= 0 always fails u < -1).
// ===================================================================
__global__ void k_mklut() {
    int m = threadIdx.x;          // 0..26
    float t;
    if (m <= 25) {
        float x = (float)(2 * m);
        float q2 = (x * x) / 50.0f;              // fp32, matches per-element path
        double prob = 0.5 * exp(-(double)q2);
        t = (float)prob;                          // round-nearest
        if ((double)t < prob)                     // bump to smallest fp32 >= prob
            t = __int_as_float(__float_as_int(t) + 1);
    } else {
        t = -1.0f;
    }
    g_lutf[m] = t;
}

// ===================================================================
// Prep: sign(W1)^T as floats via smem tile transpose (coalesced both ways)
// ===================================================================
__global__ void k_signW1(const float* __restrict__ W1) {
    __shared__ float tile[32][33];
    int k0 = blockIdx.x * 32, n0 = blockIdx.y * 32;
    int tx = threadIdx.x, ty = threadIdx.y;      // block (32, 8)
#pragma unroll
    for (int r = 0; r < 32; r += 8) {
        int n = n0 + ty + r, k = k0 + tx;
        float w = (k < K1) ? W1[(size_t)n * K1 + k] : 0.f;
        tile[ty + r][tx] = (w > 0.f) ? 1.f : ((w < 0.f) ? -1.f : 0.f);
    }
    __syncthreads();
#pragma unroll
    for (int r = 0; r < 32; r += 8) {
        int k = k0 + ty + r, n = n0 + tx;
        if (k < K1) g_sW1[(size_t)k * HH + n] = tile[tx][ty + r];
    }
}

// Pack sign bits of a weight matrix (bit=1 <=> weight>0 <=> +1)
__global__ void k_packW(const float* __restrict__ W, int which, int total) {
    int idx = blockIdx.x * 256 + threadIdx.x;
    unsigned* dst = (which == 0) ? g_w2 : (which == 1) ? g_w3 : g_w4;
    bool pos = (idx < total) ? (W[idx] > 0.f) : false;
    unsigned bal = __ballot_sync(0xffffffffu, pos);
    if ((threadIdx.x & 31) == 0 && idx < total) dst[idx >> 5] = bal;
}

// ===================================================================
// Layer 1: fp32 SGEMM  h1 = X * sW1, 128x128 tile, BK=16, double-buffered.
// Per-thread accumulation is sequential in k (FFMA chain) -> bit-identical
// to the single-buffered R3 version (and to the reference). DO NOT change
// the accumulation semantics.
// ===================================================================
__global__ __launch_bounds__(256, 2) void k_gemm1(const float* __restrict__ X) {
    __shared__ float As[2][16][128];   // [buf][k][m]
    __shared__ float Bs[2][16][128];   // [buf][k][n]
    int bn0 = blockIdx.x * 128;
    int bm0 = blockIdx.y * 128;
    int tid = threadIdx.x;
    int ty = tid >> 4, tx = tid & 15;

    // Loader addressing (two 16B loads each for A and B per thread)
    int p0 = tid * 2, p1 = tid * 2 + 1;
    int ar0 = p0 >> 2, ac0 = (p0 & 3) << 2;
    int ar1 = p1 >> 2, ac1 = (p1 & 3) << 2;
    int br0 = p0 >> 5, bc0 = (p0 & 31) << 2;
    int br1 = p1 >> 5, bc1 = (p1 & 31) << 2;
    const float* aptr0 = &X[(size_t)(bm0 + ar0) * K1 + ac0];
    const float* aptr1 = &X[(size_t)(bm0 + ar1) * K1 + ac1];
    const float* bptr0 = &g_sW1[(size_t)br0 * HH + bn0 + bc0];
    const float* bptr1 = &g_sW1[(size_t)br1 * HH + bn0 + bc1];

    float acc[8][8];
#pragma unroll
    for (int i = 0; i < 8; i++)
#pragma unroll
        for (int j = 0; j < 8; j++) acc[i][j] = 0.f;

    // Prologue: tile 0 -> buf 0
    float4 av0 = *(const float4*)aptr0;
    float4 av1 = *(const float4*)aptr1;
    float4 bv0 = *(const float4*)bptr0;
    float4 bv1 = *(const float4*)bptr1;
    As[0][ac0 + 0][ar0] = av0.x; As[0][ac0 + 1][ar0] = av0.y;
    As[0][ac0 + 2][ar0] = av0.z; As[0][ac0 + 3][ar0] = av0.w;
    As[0][ac1 + 0][ar1] = av1.x; As[0][ac1 + 1][ar1] = av1.y;
    As[0][ac1 + 2][ar1] = av1.z; As[0][ac1 + 3][ar1] = av1.w;
    *(float4*)&Bs[0][br0][bc0] = bv0;
    *(float4*)&Bs[0][br1][bc1] = bv1;
    __syncthreads();

    int buf = 0;
    for (int kt = 16; kt <= K1; kt += 16) {
        bool more = (kt < K1);
        if (more) {
            av0 = *(const float4*)(aptr0 + kt);
            av1 = *(const float4*)(aptr1 + kt);
            bv0 = *(const float4*)(bptr0 + (size_t)kt * HH);
            bv1 = *(const float4*)(bptr1 + (size_t)kt * HH);
        }
#pragma unroll
        for (int k = 0; k < 16; k++) {
            float a[8], b[8];
#pragma unroll
            for (int i = 0; i < 8; i++) a[i] = As[buf][k][ty * 8 + i];
#pragma unroll
            for (int j = 0; j < 8; j++) b[j] = Bs[buf][k][tx * 8 + j];
#pragma unroll
            for (int i = 0; i < 8; i++)
#pragma unroll
                for (int j = 0; j < 8; j++) acc[i][j] += a[i] * b[j];
        }
        if (more) {
            int nb = buf ^ 1;
            As[nb][ac0 + 0][ar0] = av0.x; As[nb][ac0 + 1][ar0] = av0.y;
            As[nb][ac0 + 2][ar0] = av0.z; As[nb][ac0 + 3][ar0] = av0.w;
            As[nb][ac1 + 0][ar1] = av1.x; As[nb][ac1 + 1][ar1] = av1.y;
            As[nb][ac1 + 2][ar1] = av1.z; As[nb][ac1 + 3][ar1] = av1.w;
            *(float4*)&Bs[nb][br0][bc0] = bv0;
            *(float4*)&Bs[nb][br1][bc1] = bv1;
            __syncthreads();
            buf = nb;
        }
    }

#pragma unroll
    for (int i = 0; i < 8; i++) {
        float* p = &g_h[(size_t)(bm0 + ty * 8 + i) * HH + bn0 + tx * 8];
        *(float4*)p       = make_float4(acc[i][0], acc[i][1], acc[i][2], acc[i][3]);
        *(float4*)(p + 4) = make_float4(acc[i][4], acc[i][5], acc[i][6], acc[i][7]);
    }
}

// ===================================================================
// BN1 stats: Kahan-compensated fp32 partials (no fp64 in hot loop).
// Partial written as (double)sum - (double)comp -> ~1e-10 accurate;
// mu perturbation << min sign margin.
// ===================================================================
__global__ __launch_bounds__(256) void k_stats1() {
    int blk = blockIdx.x;            // 0..127
    int r0 = blk * RPB;
    int t = threadIdx.x;
    float s[4] = {0, 0, 0, 0}, cs[4] = {0, 0, 0, 0};
    float q[4] = {0, 0, 0, 0}, cq[4] = {0, 0, 0, 0};
    for (int r = 0; r < RPB; r++) {
        const float* row = &g_h[(size_t)(r0 + r) * HH];
#pragma unroll
        for (int i = 0; i < 4; i++) {
            float v = row[t + 256 * i];
            float y = __fsub_rn(v, cs[i]);
            float tt = __fadd_rn(s[i], y);
            cs[i] = __fsub_rn(__fsub_rn(tt, s[i]), y);
            s[i] = tt;
            float v2 = __fmul_rn(v, v);
            float y2 = __fsub_rn(v2, cq[i]);
            float t2 = __fadd_rn(q[i], y2);
            cq[i] = __fsub_rn(__fsub_rn(t2, q[i]), y2);
            q[i] = t2;
        }
    }
#pragma unroll
    for (int i = 0; i < 4; i++) {
        g_part[blk][t + 256 * i]      = (double)s[i] - (double)cs[i];
        g_part[blk][HH + t + 256 * i] = (double)q[i] - (double)cq[i];
    }
}

__global__ void k_reduce1() {
    int c = blockIdx.x * 256 + threadIdx.x;   // 4 blocks * 256 = 1024
    double s = 0, sq = 0;
    for (int p = 0; p < NPART; p++) { s += g_part[p][c]; sq += g_part[p][HH + c]; }
    double mu = s / (double)BB;
    double var = sq / (double)BB - mu * mu;
    g_muf[c] = (float)mu;
    g_rf[c]  = (float)(1.0 / sqrt(var + 1e-5));
}

// Pack sign(batchnorm(h1)) into g_act.
__global__ void k_pack1(const float* __restrict__ gv, const float* __restrict__ bv) {
    int idx = blockIdx.x * 256 + threadIdx.x;     // BB*HH
    int c = idx & (HH - 1);
    float h = g_h[idx];
    float z = __fadd_rn(__fmul_rn(__fmul_rn(__fsub_rn(h, g_muf[c]), g_rf[c]), gv[c]), bv[c]);
    unsigned bal = __ballot_sync(0xffffffffu, z > 0.f);
    if ((threadIdx.x & 31) == 0) g_act[idx >> 5] = bal;
}

// ===================================================================
// Binary GEMM (layers 2,3): g_h[b,n] = 1024 - 2*sum_w popc(act ^ w). Bit-exact.
// ===================================================================
__global__ __launch_bounds__(256) void k_bgemm(int which) {
    __shared__ unsigned As[32][128];   // [word][m]
    __shared__ unsigned Ws[32][128];   // [word][n]
    const unsigned* __restrict__ Wb = (which == 0) ? g_w2 : g_w3;
    int bn0 = blockIdx.x * 128;
    int bm0 = blockIdx.y * 128;
    int tid = threadIdx.x;
    int ty = tid >> 4, tx = tid & 15;

#pragma unroll
    for (int i = 0; i < 4; i++) {
        int p = tid * 4 + i;                 // 0..1023
        int r = p >> 3, c4 = (p & 7) << 2;   // 128 rows x 32 words, uint4
        uint4 av = *(const uint4*)&g_act[(size_t)(bm0 + r) * NW + c4];
        As[c4 + 0][r] = av.x; As[c4 + 1][r] = av.y;
        As[c4 + 2][r] = av.z; As[c4 + 3][r] = av.w;
        uint4 wv = *(const uint4*)&Wb[(size_t)(bn0 + r) * NW + c4];
        Ws[c4 + 0][r] = wv.x; Ws[c4 + 1][r] = wv.y;
        Ws[c4 + 2][r] = wv.z; Ws[c4 + 3][r] = wv.w;
    }
    __syncthreads();

    int acc[8][8];
#pragma unroll
    for (int i = 0; i < 8; i++)
#pragma unroll
        for (int j = 0; j < 8; j++) acc[i][j] = 0;

    for (int w = 0; w < 32; w++) {
        unsigned a[8], b[8];
#pragma unroll
        for (int i = 0; i < 8; i++) a[i] = As[w][ty * 8 + i];
#pragma unroll
        for (int j = 0; j < 8; j++) b[j] = Ws[w][tx * 8 + j];
#pragma unroll
        for (int i = 0; i < 8; i++)
#pragma unroll
            for (int j = 0; j < 8; j++) acc[i][j] += __popc(a[i] ^ b[j]);
    }
#pragma unroll
    for (int i = 0; i < 8; i++) {
        float* p = &g_h[(size_t)(bm0 + ty * 8 + i) * HH + bn0 + tx * 8];
        *(float4*)p = make_float4((float)(HH - 2 * acc[i][0]), (float)(HH - 2 * acc[i][1]),
                                  (float)(HH - 2 * acc[i][2]), (float)(HH - 2 * acc[i][3]));
        *(float4*)(p + 4) = make_float4((float)(HH - 2 * acc[i][4]), (float)(HH - 2 * acc[i][5]),
                                        (float)(HH - 2 * acc[i][6]), (float)(HH - 2 * acc[i][7]));
    }
}

// ===================================================================
// noisy_binarize via fp32 threshold LUT (bit-identical to fp64 path),
// pack bits + per-block column sums of the +-1 values
// ===================================================================
__global__ __launch_bounds__(256) void k_noisy(const float* __restrict__ U) {
    __shared__ float lut[27];
    if (threadIdx.x < 27) lut[threadIdx.x] = g_lutf[threadIdx.x];
    __syncthreads();

    int blk = blockIdx.x;       // 0..127
    int r0 = blk * RPB;
    int t = threadIdx.x;
    int lane = t & 31;
    int isum[4] = {0, 0, 0, 0};
    for (int r = 0; r < RPB; r++) {
        size_t base = (size_t)(r0 + r) * HH;
#pragma unroll
        for (int q = 0; q < 4; q++) {
            int c = t + 256 * q;
            float x = g_h[base + c];
            float uu = U[base + c];
            int m = ((int)fabsf(x)) >> 1;      // x is an even integer
            if (m > 26) m = 26;
            bool spos = (x > 0.f);
            bool flip = (uu < lut[m]);          // == ((double)uu < prob) exactly
            bool pos = spos ^ flip;
            isum[q] += pos ? 1 : -1;
            unsigned bal = __ballot_sync(0xffffffffu, pos);
            if (lane == 0) g_nv[(base + c) >> 5] = bal;
        }
    }
#pragma unroll
    for (int q = 0; q < 4; q++) g_part[blk][t + 256 * q] = (double)isum[q];
}

// Per-column BN+sign LUT masks: out_bit = (nv_bit & sel) ^ mb.
__global__ void k_lut(const float* __restrict__ gv, const float* __restrict__ bv) {
    int c = threadIdx.x;        // 1024 threads, one block
    double s = 0;
    for (int p = 0; p < NPART; p++) s += g_part[p][c];
    double mu = s / (double)BB;
    double r = 1.0 / sqrt(1.0 - mu * mu + 1e-5);
    double zp = (( 1.0 - mu) * r) * (double)gv[c] + (double)bv[c];
    double zm = ((-1.0 - mu) * r) * (double)gv[c] + (double)bv[c];
    unsigned pb = __ballot_sync(0xffffffffu, zp > 0.0);
    unsigned mb = __ballot_sync(0xffffffffu, zm > 0.0);
    if ((c & 31) == 0) {
        g_sel[c >> 5] = pb ^ mb;
        g_mb[c >> 5]  = mb;
    }
}

__global__ void k_apply() {
    int i = blockIdx.x * 256 + threadIdx.x;   // BB*NW
    int w = i & (NW - 1);
    g_act[i] = (g_nv[i] & g_sel[w]) ^ g_mb[w];
}

// ===================================================================
// Output layer: out[b,o] = 1024 - 2*sum_w popc(act ^ w4[o])
// ===================================================================
__global__ __launch_bounds__(256) void k_out(float* __restrict__ outp) {
    __shared__ unsigned As[256][33];
    __shared__ unsigned W4s[NOUT][NW];
    int r0 = blockIdx.x * 256;
    int t = threadIdx.x;
#pragma unroll
    for (int i = 0; i < 32; i++) {
        int p = t + 256 * i;
        As[p >> 5][p & 31] = g_act[(size_t)r0 * NW + p];
    }
    for (int i = t; i < NOUT * NW; i += 256) ((unsigned*)W4s)[i] = g_w4[i];
    __syncthreads();
#pragma unroll
    for (int o = 0; o < NOUT; o++) {
        int cnt = 0;
#pragma unroll
        for (int w = 0; w < NW; w++) cnt += __popc(As[t][w] ^ W4s[o][w]);
        outp[(size_t)(r0 + t) * NOUT + o] = (float)(HH - 2 * cnt);
    }
}

// ===================================================================
// Launch. Input order: x, u2, u3, W1, W2, W3, W4, g1, b1, g2, b2, g3, b3
// ===================================================================
extern "C" void kernel_launch(void* const* d_in, const int* in_sizes, int n_in,
                              void* d_out, int out_size) {
    const float* x  = (const float*)d_in[0];
    const float* u2 = (const float*)d_in[1];
    const float* u3 = (const float*)d_in[2];
    const float* W1 = (const float*)d_in[3];
    const float* W2 = (const float*)d_in[4];
    const float* W3 = (const float*)d_in[5];
    const float* W4 = (const float*)d_in[6];
    const float* g1 = (const float*)d_in[7];
    const float* b1 = (const float*)d_in[8];
    const float* g2 = (const float*)d_in[9];
    const float* b2 = (const float*)d_in[10];
    const float* g3 = (const float*)d_in[11];
    const float* b3 = (const float*)d_in[12];
    float* out = (float*)d_out;

    // Prep
    k_mklut<<<1, 27>>>();
    {
        dim3 tb(32, 8), tg((K1 + 31) / 32, HH / 32);
        k_signW1<<<tg, tb>>>(W1);
    }
    k_packW<<<(HH * HH) / 256, 256>>>(W2, 0, HH * HH);
    k_packW<<<(HH * HH) / 256, 256>>>(W3, 1, HH * HH);
    k_packW<<<(NOUT * HH + 255) / 256, 256>>>(W4, 2, NOUT * HH);

    dim3 ggrid(HH / 128, BB / 128);   // (8, 128)

    // Layer 1
    k_gemm1<<<ggrid, 256>>>(x);
    k_stats1<<<NPART, 256>>>();
    k_reduce1<<<HH / 256, 256>>>();
    k_pack1<<<(BB * HH) / 256, 256>>>(g1, b1);

    // Layer 2
    k_bgemm<<<ggrid, 256>>>(0);
    k_noisy<<<NPART, 256>>>(u2);
    k_lut<<<1, HH>>>(g2, b2);
    k_apply<<<(BB * NW) / 256, 256>>>();

    // Layer 3
    k_bgemm<<<ggrid, 256>>>(1);
    k_noisy<<<NPART, 256>>>(u3);
    k_lut<<<1, HH>>>(g3, b3);
    k_apply<<<(BB * NW) / 256, 256>>>();

    // Output layer
    k_out<<<BB / 256, 256>>>(out);
}

// round 7
// speedup vs baseline: 1.7661x; 1.5583x over previous
#include <cuda_runtime.h>
#include <cstdint>
#include <math.h>

// ===== Problem dims =====
#define BB   16384
#define K1   784
#define HH   1024
#define NW   32          // HH/32 packed words per row
#define NOUT 10
#define NPART 128
#define RPB  (BB/NPART)

// ===== Scratch (device globals) =====
__device__ float    g_h[(size_t)BB*HH];     // layer-1 preactivations only
__device__ unsigned g_nv[BB*NW];
__device__ unsigned g_act[BB*NW];
__device__ float    g_sW1[K1*HH];           // sign(W1)^T, [k][n]
__device__ unsigned g_w2[HH*NW];
__device__ unsigned g_w3[HH*NW];
__device__ unsigned g_w4[NOUT*NW];
__device__ double   g_part[NPART][2*HH];
__device__ float    g_muf[HH];
__device__ float    g_rf[HH];
__device__ unsigned g_sel[NW];
__device__ unsigned g_mb[NW];
__device__ float    g_lutf[27];

// packed f32x2 fma: both halves round independently (rn), so each half's
// accumulation chain is bit-identical to scalar FFMA in the same order.
__device__ __forceinline__ unsigned long long fma2(unsigned long long a,
                                                   unsigned long long b,
                                                   unsigned long long c) {
    unsigned long long d;
    asm("fma.rn.f32x2 %0, %1, %2, %3;" : "=l"(d) : "l"(a), "l"(b), "l"(c));
    return d;
}
__device__ __forceinline__ unsigned long long dup2(float a) {
    unsigned long long d;
    asm("mov.b64 %0, {%1, %1};" : "=l"(d) : "r"(__float_as_uint(a)));
    return d;
}

// ===================================================================
// Flip-threshold LUT: t[m] = smallest fp32 >= 0.5*exp(-((2m)^2/50)),
// so (u < t[m]) <=> ((double)u < prob) exactly. m>=26 -> never flip.
// ===================================================================
__global__ void k_mklut() {
    int m = threadIdx.x;          // 0..26
    float t;
    if (m <= 25) {
        float x = (float)(2 * m);
        float q2 = (x * x) / 50.0f;
        double prob = 0.5 * exp(-(double)q2);
        t = (float)prob;
        if ((double)t < prob) t = __int_as_float(__float_as_int(t) + 1);
    } else t = -1.0f;
    g_lutf[m] = t;
}

// sign(W1)^T via smem tile transpose
__global__ void k_signW1(const float* __restrict__ W1) {
    __shared__ float tile[32][33];
    int k0 = blockIdx.x * 32, n0 = blockIdx.y * 32;
    int tx = threadIdx.x, ty = threadIdx.y;      // (32, 8)
#pragma unroll
    for (int r = 0; r < 32; r += 8) {
        int n = n0 + ty + r, k = k0 + tx;
        float w = (k < K1) ? W1[(size_t)n * K1 + k] : 0.f;
        tile[ty + r][tx] = (w > 0.f) ? 1.f : ((w < 0.f) ? -1.f : 0.f);
    }
    __syncthreads();
#pragma unroll
    for (int r = 0; r < 32; r += 8) {
        int k = k0 + ty + r, n = n0 + tx;
        if (k < K1) g_sW1[(size_t)k * HH + n] = tile[tx][ty + r];
    }
}

__global__ void k_packW(const float* __restrict__ W, int which, int total) {
    int idx = blockIdx.x * 256 + threadIdx.x;
    unsigned* dst = (which == 0) ? g_w2 : (which == 1) ? g_w3 : g_w4;
    bool pos = (idx < total) ? (W[idx] > 0.f) : false;
    unsigned bal = __ballot_sync(0xffffffffu, pos);
    if ((threadIdx.x & 31) == 0 && idx < total) dst[idx >> 5] = bal;
}

// ===================================================================
// Layer 1 SGEMM, 128x128xBK16, double-buffered, f32x2 packed FMA.
// Per-output chain: single accumulator, k ascending -> bit-identical
// to scalar sequential FFMA. DO NOT change accumulation semantics.
// ===================================================================
__global__ __launch_bounds__(256, 2) void k_gemm1(const float* __restrict__ X) {
    __shared__ float As[2][16][128];
    __shared__ float Bs[2][16][128];
    int bn0 = blockIdx.x * 128;
    int bm0 = blockIdx.y * 128;
    int tid = threadIdx.x;
    int ty = tid >> 4, tx = tid & 15;

    int p0 = tid * 2, p1 = tid * 2 + 1;
    int ar0 = p0 >> 2, ac0 = (p0 & 3) << 2;
    int ar1 = p1 >> 2, ac1 = (p1 & 3) << 2;
    int br0 = p0 >> 5, bc0 = (p0 & 31) << 2;
    int br1 = p1 >> 5, bc1 = (p1 & 31) << 2;
    const float* aptr0 = &X[(size_t)(bm0 + ar0) * K1 + ac0];
    const float* aptr1 = &X[(size_t)(bm0 + ar1) * K1 + ac1];
    const float* bptr0 = &g_sW1[(size_t)br0 * HH + bn0 + bc0];
    const float* bptr1 = &g_sW1[(size_t)br1 * HH + bn0 + bc1];

    unsigned long long acc2[8][4];   // [row i][col-pair q] = cols {2q, 2q+1}
#pragma unroll
    for (int i = 0; i < 8; i++)
#pragma unroll
        for (int q = 0; q < 4; q++) acc2[i][q] = 0ULL;

    float4 av0 = *(const float4*)aptr0;
    float4 av1 = *(const float4*)aptr1;
    float4 bv0 = *(const float4*)bptr0;
    float4 bv1 = *(const float4*)bptr1;
    As[0][ac0 + 0][ar0] = av0.x; As[0][ac0 + 1][ar0] = av0.y;
    As[0][ac0 + 2][ar0] = av0.z; As[0][ac0 + 3][ar0] = av0.w;
    As[0][ac1 + 0][ar1] = av1.x; As[0][ac1 + 1][ar1] = av1.y;
    As[0][ac1 + 2][ar1] = av1.z; As[0][ac1 + 3][ar1] = av1.w;
    *(float4*)&Bs[0][br0][bc0] = bv0;
    *(float4*)&Bs[0][br1][bc1] = bv1;
    __syncthreads();

    int buf = 0;
    for (int kt = 16; kt <= K1; kt += 16) {
        bool more = (kt < K1);
        if (more) {
            av0 = *(const float4*)(aptr0 + kt);
            av1 = *(const float4*)(aptr1 + kt);
            bv0 = *(const float4*)(bptr0 + (size_t)kt * HH);
            bv1 = *(const float4*)(bptr1 + (size_t)kt * HH);
        }
#pragma unroll
        for (int k = 0; k < 16; k++) {
            // a: 8 floats; b: 4 packed pairs (memory float2 == f32x2 lo/hi)
            float4 a0 = *(const float4*)&As[buf][k][ty * 8];
            float4 a1 = *(const float4*)&As[buf][k][ty * 8 + 4];
            ulonglong2 b01 = *(const ulonglong2*)&Bs[buf][k][tx * 8];
            ulonglong2 b23 = *(const ulonglong2*)&Bs[buf][k][tx * 8 + 4];
            unsigned long long bq[4] = {b01.x, b01.y, b23.x, b23.y};
            float a[8] = {a0.x, a0.y, a0.z, a0.w, a1.x, a1.y, a1.z, a1.w};
#pragma unroll
            for (int i = 0; i < 8; i++) {
                unsigned long long ai = dup2(a[i]);
#pragma unroll
                for (int q = 0; q < 4; q++)
                    acc2[i][q] = fma2(ai, bq[q], acc2[i][q]);
            }
        }
        if (more) {
            int nb = buf ^ 1;
            As[nb][ac0 + 0][ar0] = av0.x; As[nb][ac0 + 1][ar0] = av0.y;
            As[nb][ac0 + 2][ar0] = av0.z; As[nb][ac0 + 3][ar0] = av0.w;
            As[nb][ac1 + 0][ar1] = av1.x; As[nb][ac1 + 1][ar1] = av1.y;
            As[nb][ac1 + 2][ar1] = av1.z; As[nb][ac1 + 3][ar1] = av1.w;
            *(float4*)&Bs[nb][br0][bc0] = bv0;
            *(float4*)&Bs[nb][br1][bc1] = bv1;
            __syncthreads();
            buf = nb;
        }
    }

#pragma unroll
    for (int i = 0; i < 8; i++) {
        unsigned long long* p =
            (unsigned long long*)&g_h[(size_t)(bm0 + ty * 8 + i) * HH + bn0 + tx * 8];
        *(ulonglong2*)p       = make_ulonglong2(acc2[i][0], acc2[i][1]);
        *(ulonglong2*)(p + 2) = make_ulonglong2(acc2[i][2], acc2[i][3]);
    }
}

// ===================================================================
// BN1 stats: Kahan fp32 partials (mu error ~1e-10, safe vs ~1e-6 margins)
// ===================================================================
__global__ __launch_bounds__(256) void k_stats1() {
    int blk = blockIdx.x;
    int r0 = blk * RPB;
    int t = threadIdx.x;
    float s[4] = {0,0,0,0}, cs[4] = {0,0,0,0};
    float q[4] = {0,0,0,0}, cq[4] = {0,0,0,0};
    for (int r = 0; r < RPB; r++) {
        const float* row = &g_h[(size_t)(r0 + r) * HH];
#pragma unroll
        for (int i = 0; i < 4; i++) {
            float v = row[t + 256 * i];
            float y = __fsub_rn(v, cs[i]);
            float tt = __fadd_rn(s[i], y);
            cs[i] = __fsub_rn(__fsub_rn(tt, s[i]), y);
            s[i] = tt;
            float v2 = __fmul_rn(v, v);
            float y2 = __fsub_rn(v2, cq[i]);
            float t2 = __fadd_rn(q[i], y2);
            cq[i] = __fsub_rn(__fsub_rn(t2, q[i]), y2);
            q[i] = t2;
        }
    }
#pragma unroll
    for (int i = 0; i < 4; i++) {
        g_part[blk][t + 256 * i]      = (double)s[i] - (double)cs[i];
        g_part[blk][HH + t + 256 * i] = (double)q[i] - (double)cq[i];
    }
}

__global__ void k_reduce1() {
    int c = blockIdx.x * 256 + threadIdx.x;
    double s = 0, sq = 0;
    for (int p = 0; p < NPART; p++) { s += g_part[p][c]; sq += g_part[p][HH + c]; }
    double mu = s / (double)BB;
    double var = sq / (double)BB - mu * mu;
    g_muf[c] = (float)mu;
    g_rf[c]  = (float)(1.0 / sqrt(var + 1e-5));
}

__global__ void k_pack1(const float* __restrict__ gv, const float* __restrict__ bv) {
    int idx = blockIdx.x * 256 + threadIdx.x;
    int c = idx & (HH - 1);
    float h = g_h[idx];
    float z = __fadd_rn(__fmul_rn(__fmul_rn(__fsub_rn(h, g_muf[c]), g_rf[c]), gv[c]), bv[c]);
    unsigned bal = __ballot_sync(0xffffffffu, z > 0.f);
    if ((threadIdx.x & 31) == 0) g_act[idx >> 5] = bal;
}

// ===================================================================
// Fused binary GEMM + noisy_binarize + bit-pack + column-sums.
// h[b,n] = 1024 - 2*popc-sum (exact int). Epilogue never touches g_h.
// Writes packed nv bits to g_nv and per-bm column sums to g_part.
// ===================================================================
__global__ __launch_bounds__(256) void k_bgemm_fused(int which, const float* __restrict__ U) {
    __shared__ unsigned As[32][128];
    __shared__ unsigned Ws[32][128];
    __shared__ float lut[27];
    __shared__ unsigned char sbits[128][16];   // [row][byte] = 8 col-bits
    __shared__ int icol[128][17];              // [col][ty] partial colsums

    const unsigned* __restrict__ Wb = (which == 0) ? g_w2 : g_w3;
    int bn0 = blockIdx.x * 128;
    int bm0 = blockIdx.y * 128;
    int tid = threadIdx.x;
    int ty = tid >> 4, tx = tid & 15;

    if (tid < 27) lut[tid] = g_lutf[tid];

#pragma unroll
    for (int i = 0; i < 4; i++) {
        int p = tid * 4 + i;
        int r = p >> 3, c4 = (p & 7) << 2;
        uint4 av = *(const uint4*)&g_act[(size_t)(bm0 + r) * NW + c4];
        As[c4 + 0][r] = av.x; As[c4 + 1][r] = av.y;
        As[c4 + 2][r] = av.z; As[c4 + 3][r] = av.w;
        uint4 wv = *(const uint4*)&Wb[(size_t)(bn0 + r) * NW + c4];
        Ws[c4 + 0][r] = wv.x; Ws[c4 + 1][r] = wv.y;
        Ws[c4 + 2][r] = wv.z; Ws[c4 + 3][r] = wv.w;
    }
    __syncthreads();

    int acc[8][8];
#pragma unroll
    for (int i = 0; i < 8; i++)
#pragma unroll
        for (int j = 0; j < 8; j++) acc[i][j] = 0;

    for (int w = 0; w < 32; w++) {
        unsigned a[8], b[8];
#pragma unroll
        for (int i = 0; i < 8; i++) a[i] = As[w][ty * 8 + i];
#pragma unroll
        for (int j = 0; j < 8; j++) b[j] = Ws[w][tx * 8 + j];
#pragma unroll
        for (int i = 0; i < 8; i++)
#pragma unroll
            for (int j = 0; j < 8; j++) acc[i][j] += __popc(a[i] ^ b[j]);
    }

    // Epilogue: noisy binarize + byte-pack + column sums (all exact int)
    int csum[8];
#pragma unroll
    for (int j = 0; j < 8; j++) csum[j] = 0;
#pragma unroll
    for (int i = 0; i < 8; i++) {
        int rowg = bm0 + ty * 8 + i;
        float4 u0 = *(const float4*)&U[(size_t)rowg * HH + bn0 + tx * 8];
        float4 u1 = *(const float4*)&U[(size_t)rowg * HH + bn0 + tx * 8 + 4];
        float uu[8] = {u0.x, u0.y, u0.z, u0.w, u1.x, u1.y, u1.z, u1.w};
        unsigned byte = 0;
#pragma unroll
        for (int j = 0; j < 8; j++) {
            int cnt = acc[i][j];
            int hs = 512 - cnt;                 // h/2
            int m = (hs < 0) ? -hs : hs;
            if (m > 26) m = 26;
            bool pos = (hs > 0) ^ (uu[j] < lut[m]);
            byte |= (pos ? 1u : 0u) << j;
            csum[j] += pos ? 1 : -1;
        }
        sbits[ty * 8 + i][tx] = (unsigned char)byte;
    }
#pragma unroll
    for (int j = 0; j < 8; j++) icol[tx * 8 + j][ty] = csum[j];
    __syncthreads();

    // assemble 32-bit words: 128 rows x 4 words; 2 per thread
#pragma unroll
    for (int v = 0; v < 2; v++) {
        int wi = tid * 2 + v;                  // 0..511
        int row = wi >> 2, w = wi & 3;
        unsigned word = *(const unsigned*)&sbits[row][w * 4];
        g_nv[(size_t)(bm0 + row) * NW + blockIdx.x * 4 + w] = word;
    }
    // column sums: 128 cols, fixed-order 16-way int sum
    if (tid < 128) {
        int s = 0;
#pragma unroll
        for (int t = 0; t < 16; t++) s += icol[tid][t];
        g_part[blockIdx.y][bn0 + tid] = (double)s;
    }
}

// Per-column BN+sign LUT masks: out_bit = (nv_bit & sel) ^ mb.
__global__ void k_lut(const float* __restrict__ gv, const float* __restrict__ bv) {
    int c = threadIdx.x;        // 1024 threads
    double s = 0;
    for (int p = 0; p < NPART; p++) s += g_part[p][c];
    double mu = s / (double)BB;
    double r = 1.0 / sqrt(1.0 - mu * mu + 1e-5);
    double zp = (( 1.0 - mu) * r) * (double)gv[c] + (double)bv[c];
    double zm = ((-1.0 - mu) * r) * (double)gv[c] + (double)bv[c];
    unsigned pb = __ballot_sync(0xffffffffu, zp > 0.0);
    unsigned mb = __ballot_sync(0xffffffffu, zm > 0.0);
    if ((c & 31) == 0) {
        g_sel[c >> 5] = pb ^ mb;
        g_mb[c >> 5]  = mb;
    }
}

__global__ void k_apply() {
    int i = blockIdx.x * 256 + threadIdx.x;
    int w = i & (NW - 1);
    g_act[i] = (g_nv[i] & g_sel[w]) ^ g_mb[w];
}

// Output layer
__global__ __launch_bounds__(256) void k_out(float* __restrict__ outp) {
    __shared__ unsigned As[256][33];
    __shared__ unsigned W4s[NOUT][NW];
    int r0 = blockIdx.x * 256;
    int t = threadIdx.x;
#pragma unroll
    for (int i = 0; i < 32; i++) {
        int p = t + 256 * i;
        As[p >> 5][p & 31] = g_act[(size_t)r0 * NW + p];
    }
    for (int i = t; i < NOUT * NW; i += 256) ((unsigned*)W4s)[i] = g_w4[i];
    __syncthreads();
#pragma unroll
    for (int o = 0; o < NOUT; o++) {
        int cnt = 0;
#pragma unroll
        for (int w = 0; w < NW; w++) cnt += __popc(As[t][w] ^ W4s[o][w]);
        outp[(size_t)(r0 + t) * NOUT + o] = (float)(HH - 2 * cnt);
    }
}

// ===================================================================
extern "C" void kernel_launch(void* const* d_in, const int* in_sizes, int n_in,
                              void* d_out, int out_size) {
    const float* x  = (const float*)d_in[0];
    const float* u2 = (const float*)d_in[1];
    const float* u3 = (const float*)d_in[2];
    const float* W1 = (const float*)d_in[3];
    const float* W2 = (const float*)d_in[4];
    const float* W3 = (const float*)d_in[5];
    const float* W4 = (const float*)d_in[6];
    const float* g1 = (const float*)d_in[7];
    const float* b1 = (const float*)d_in[8];
    const float* g2 = (const float*)d_in[9];
    const float* b2 = (const float*)d_in[10];
    const float* g3 = (const float*)d_in[11];
    const float* b3 = (const float*)d_in[12];
    float* out = (float*)d_out;

    k_mklut<<<1, 27>>>();
    {
        dim3 tb(32, 8), tg((K1 + 31) / 32, HH / 32);
        k_signW1<<<tg, tb>>>(W1);
    }
    k_packW<<<(HH * HH) / 256, 256>>>(W2, 0, HH * HH);
    k_packW<<<(HH * HH) / 256, 256>>>(W3, 1, HH * HH);
    k_packW<<<(NOUT * HH + 255) / 256, 256>>>(W4, 2, NOUT * HH);

    dim3 ggrid(HH / 128, BB / 128);

    // Layer 1
    k_gemm1<<<ggrid, 256>>>(x);
    k_stats1<<<NPART, 256>>>();
    k_reduce1<<<HH / 256, 256>>>();
    k_pack1<<<(BB * HH) / 256, 256>>>(g1, b1);

    // Layer 2 (fused GEMM+noisy)
    k_bgemm_fused<<<ggrid, 256>>>(0, u2);
    k_lut<<<1, HH>>>(g2, b2);
    k_apply<<<(BB * NW) / 256, 256>>>();

    // Layer 3
    k_bgemm_fused<<<ggrid, 256>>>(1, u3);
    k_lut<<<1, HH>>>(g3, b3);
    k_apply<<<(BB * NW) / 256, 256>>>();

    // Output layer
    k_out<<<BB / 256, 256>>>(out);
}

// round 8
// speedup vs baseline: 1.7764x; 1.0059x over previous
#include <cuda_runtime.h>
#include <cstdint>
#include <math.h>

// ===== Problem dims =====
#define BB   16384
#define K1   784
#define HH   1024
#define NW   32          // HH/32 packed words per row
#define NOUT 10
#define NPART 128
#define RPB  (BB/NPART)

// ===== Scratch (device globals) =====
__device__ float    g_h[(size_t)BB*HH];     // layer-1 preactivations only
__device__ unsigned g_nv[BB*NW];
__device__ unsigned g_act[BB*NW];
__device__ float    g_sW1[K1*HH];           // sign(W1)^T, [k][n]
__device__ unsigned g_w2[HH*NW];
__device__ unsigned g_w3[HH*NW];
__device__ unsigned g_w4[NOUT*NW];
__device__ double   g_part[NPART][2*HH];
__device__ float    g_muf[HH];
__device__ float    g_rf[HH];
__device__ unsigned g_sel[NW];
__device__ unsigned g_mb[NW];
__device__ float    g_lutf[27];

// packed f32x2 fma: both halves round independently (rn) -> each half's
// chain is bit-identical to scalar FFMA in the same order.
__device__ __forceinline__ unsigned long long fma2(unsigned long long a,
                                                   unsigned long long b,
                                                   unsigned long long c) {
    unsigned long long d;
    asm("fma.rn.f32x2 %0, %1, %2, %3;" : "=l"(d) : "l"(a), "l"(b), "l"(c));
    return d;
}
__device__ __forceinline__ unsigned long long dup2(float a) {
    unsigned long long d;
    asm("mov.b64 %0, {%1, %1};" : "=l"(d) : "r"(__float_as_uint(a)));
    return d;
}
__device__ __forceinline__ void kadd(float v, float& s, float& c) {
    float y = __fsub_rn(v, c);
    float t = __fadd_rn(s, y);
    c = __fsub_rn(__fsub_rn(t, s), y);
    s = t;
}

// ===================================================================
// Flip-threshold LUT: t[m] = smallest fp32 >= 0.5*exp(-((2m)^2/50)),
// so (u < t[m]) <=> ((double)u < prob) exactly. m>=26 -> never flip.
// ===================================================================
__global__ void k_mklut() {
    int m = threadIdx.x;          // 0..26
    float t;
    if (m <= 25) {
        float x = (float)(2 * m);
        float q2 = (x * x) / 50.0f;
        double prob = 0.5 * exp(-(double)q2);
        t = (float)prob;
        if ((double)t < prob) t = __int_as_float(__float_as_int(t) + 1);
    } else t = -1.0f;
    g_lutf[m] = t;
}

// sign(W1)^T via smem tile transpose
__global__ void k_signW1(const float* __restrict__ W1) {
    __shared__ float tile[32][33];
    int k0 = blockIdx.x * 32, n0 = blockIdx.y * 32;
    int tx = threadIdx.x, ty = threadIdx.y;      // (32, 8)
#pragma unroll
    for (int r = 0; r < 32; r += 8) {
        int n = n0 + ty + r, k = k0 + tx;
        float w = (k < K1) ? W1[(size_t)n * K1 + k] : 0.f;
        tile[ty + r][tx] = (w > 0.f) ? 1.f : ((w < 0.f) ? -1.f : 0.f);
    }
    __syncthreads();
#pragma unroll
    for (int r = 0; r < 32; r += 8) {
        int k = k0 + ty + r, n = n0 + tx;
        if (k < K1) g_sW1[(size_t)k * HH + n] = tile[tx][ty + r];
    }
}

// Single kernel packs W2, W3, W4 sign bits (segment boundaries are 32-aligned)
#define W2_ELEMS (HH*HH)
#define W4_ELEMS (NOUT*HH)
__global__ void k_packAll(const float* __restrict__ W2,
                          const float* __restrict__ W3,
                          const float* __restrict__ W4) {
    int idx = blockIdx.x * 256 + threadIdx.x;
    const float* W; unsigned* dst; int off;
    if (idx < W2_ELEMS)               { W = W2; dst = g_w2; off = 0; }
    else if (idx < 2 * W2_ELEMS)      { W = W3; dst = g_w3; off = W2_ELEMS; }
    else                              { W = W4; dst = g_w4; off = 2 * W2_ELEMS; }
    int li = idx - off;
    bool pos = (idx < 2 * W2_ELEMS + W4_ELEMS) ? (W[li] > 0.f) : false;
    unsigned bal = __ballot_sync(0xffffffffu, pos);
    if ((threadIdx.x & 31) == 0 && idx < 2 * W2_ELEMS + W4_ELEMS) dst[li >> 5] = bal;
}

// ===================================================================
// Layer 1 SGEMM, 128x128xBK16, double-buffered, f32x2 packed FMA,
// with fused BN1 column-stats epilogue (Kahan fp32 -> double partials).
// Per-output FFMA chain: single accumulator, k ascending -> bit-identical.
// ===================================================================
__global__ __launch_bounds__(256, 2) void k_gemm1(const float* __restrict__ X) {
    __shared__ union {
        struct { float As[2][16][128]; float Bs[2][16][128]; } g;   // 32 KB
        struct { float s[16][128]; float c[16][128];
                 float q[16][128]; float cq[16][128]; } st;         // 32 KB
    } sm;
    int bn0 = blockIdx.x * 128;
    int bm0 = blockIdx.y * 128;
    int tid = threadIdx.x;
    int ty = tid >> 4, tx = tid & 15;

    int p0 = tid * 2, p1 = tid * 2 + 1;
    int ar0 = p0 >> 2, ac0 = (p0 & 3) << 2;
    int ar1 = p1 >> 2, ac1 = (p1 & 3) << 2;
    int br0 = p0 >> 5, bc0 = (p0 & 31) << 2;
    int br1 = p1 >> 5, bc1 = (p1 & 31) << 2;
    const float* aptr0 = &X[(size_t)(bm0 + ar0) * K1 + ac0];
    const float* aptr1 = &X[(size_t)(bm0 + ar1) * K1 + ac1];
    const float* bptr0 = &g_sW1[(size_t)br0 * HH + bn0 + bc0];
    const float* bptr1 = &g_sW1[(size_t)br1 * HH + bn0 + bc1];

    unsigned long long acc2[8][4];   // [row i][col-pair q] = cols {2q, 2q+1}
#pragma unroll
    for (int i = 0; i < 8; i++)
#pragma unroll
        for (int q = 0; q < 4; q++) acc2[i][q] = 0ULL;

    float4 av0 = *(const float4*)aptr0;
    float4 av1 = *(const float4*)aptr1;
    float4 bv0 = *(const float4*)bptr0;
    float4 bv1 = *(const float4*)bptr1;
    sm.g.As[0][ac0 + 0][ar0] = av0.x; sm.g.As[0][ac0 + 1][ar0] = av0.y;
    sm.g.As[0][ac0 + 2][ar0] = av0.z; sm.g.As[0][ac0 + 3][ar0] = av0.w;
    sm.g.As[0][ac1 + 0][ar1] = av1.x; sm.g.As[0][ac1 + 1][ar1] = av1.y;
    sm.g.As[0][ac1 + 2][ar1] = av1.z; sm.g.As[0][ac1 + 3][ar1] = av1.w;
    *(float4*)&sm.g.Bs[0][br0][bc0] = bv0;
    *(float4*)&sm.g.Bs[0][br1][bc1] = bv1;
    __syncthreads();

    int buf = 0;
    for (int kt = 16; kt <= K1; kt += 16) {
        bool more = (kt < K1);
        if (more) {
            av0 = *(const float4*)(aptr0 + kt);
            av1 = *(const float4*)(aptr1 + kt);
            bv0 = *(const float4*)(bptr0 + (size_t)kt * HH);
            bv1 = *(const float4*)(bptr1 + (size_t)kt * HH);
        }
#pragma unroll
        for (int k = 0; k < 16; k++) {
            float4 a0 = *(const float4*)&sm.g.As[buf][k][ty * 8];
            float4 a1 = *(const float4*)&sm.g.As[buf][k][ty * 8 + 4];
            ulonglong2 b01 = *(const ulonglong2*)&sm.g.Bs[buf][k][tx * 8];
            ulonglong2 b23 = *(const ulonglong2*)&sm.g.Bs[buf][k][tx * 8 + 4];
            unsigned long long bq[4] = {b01.x, b01.y, b23.x, b23.y};
            float a[8] = {a0.x, a0.y, a0.z, a0.w, a1.x, a1.y, a1.z, a1.w};
#pragma unroll
            for (int i = 0; i < 8; i++) {
                unsigned long long ai = dup2(a[i]);
#pragma unroll
                for (int q = 0; q < 4; q++)
                    acc2[i][q] = fma2(ai, bq[q], acc2[i][q]);
            }
        }
        if (more) {
            int nb = buf ^ 1;
            sm.g.As[nb][ac0 + 0][ar0] = av0.x; sm.g.As[nb][ac0 + 1][ar0] = av0.y;
            sm.g.As[nb][ac0 + 2][ar0] = av0.z; sm.g.As[nb][ac0 + 3][ar0] = av0.w;
            sm.g.As[nb][ac1 + 0][ar1] = av1.x; sm.g.As[nb][ac1 + 1][ar1] = av1.y;
            sm.g.As[nb][ac1 + 2][ar1] = av1.z; sm.g.As[nb][ac1 + 3][ar1] = av1.w;
            *(float4*)&sm.g.Bs[nb][br0][bc0] = bv0;
            *(float4*)&sm.g.Bs[nb][br1][bc1] = bv1;
            __syncthreads();
            buf = nb;
        }
    }

    // Store h + per-thread Kahan column stats (8 rows each, ascending i)
    float ss[8] = {0,0,0,0,0,0,0,0}, sc[8] = {0,0,0,0,0,0,0,0};
    float qs[8] = {0,0,0,0,0,0,0,0}, qc[8] = {0,0,0,0,0,0,0,0};
#pragma unroll
    for (int i = 0; i < 8; i++) {
        unsigned long long* p =
            (unsigned long long*)&g_h[(size_t)(bm0 + ty * 8 + i) * HH + bn0 + tx * 8];
        *(ulonglong2*)p       = make_ulonglong2(acc2[i][0], acc2[i][1]);
        *(ulonglong2*)(p + 2) = make_ulonglong2(acc2[i][2], acc2[i][3]);
#pragma unroll
        for (int q = 0; q < 4; q++) {
            float2 v2 = *(float2*)&acc2[i][q];
            kadd(v2.x, ss[2*q],   sc[2*q]);
            kadd(__fmul_rn(v2.x, v2.x), qs[2*q],   qc[2*q]);
            kadd(v2.y, ss[2*q+1], sc[2*q+1]);
            kadd(__fmul_rn(v2.y, v2.y), qs[2*q+1], qc[2*q+1]);
        }
    }
    __syncthreads();   // all As/Bs reads done; safe to reuse smem
#pragma unroll
    for (int j = 0; j < 8; j++) {
        int col = tx * 8 + j;
        sm.st.s[ty][col]  = ss[j];
        sm.st.c[ty][col]  = sc[j];
        sm.st.q[ty][col]  = qs[j];
        sm.st.cq[ty][col] = qc[j];
    }
    __syncthreads();
    if (tid < 128) {
        double sd = 0, qd = 0;
#pragma unroll
        for (int t = 0; t < 16; t++) {
            sd += (double)sm.st.s[t][tid] - (double)sm.st.c[t][tid];
            qd += (double)sm.st.q[t][tid] - (double)sm.st.cq[t][tid];
        }
        g_part[blockIdx.y][bn0 + tid]      = sd;
        g_part[blockIdx.y][HH + bn0 + tid] = qd;
    }
}

__global__ void k_reduce1() {
    int c = blockIdx.x * 256 + threadIdx.x;
    double s = 0, sq = 0;
    for (int p = 0; p < NPART; p++) { s += g_part[p][c]; sq += g_part[p][HH + c]; }
    double mu = s / (double)BB;
    double var = sq / (double)BB - mu * mu;
    g_muf[c] = (float)mu;
    g_rf[c]  = (float)(1.0 / sqrt(var + 1e-5));
}

__global__ void k_pack1(const float* __restrict__ gv, const float* __restrict__ bv) {
    int idx = blockIdx.x * 256 + threadIdx.x;
    int c = idx & (HH - 1);
    float h = g_h[idx];
    float z = __fadd_rn(__fmul_rn(__fmul_rn(__fsub_rn(h, g_muf[c]), g_rf[c]), gv[c]), bv[c]);
    unsigned bal = __ballot_sync(0xffffffffu, z > 0.f);
    if ((threadIdx.x & 31) == 0) g_act[idx >> 5] = bal;
}

// ===================================================================
// Fused binary GEMM + noisy_binarize + bit-pack + column-sums (exact int)
// ===================================================================
__global__ __launch_bounds__(256) void k_bgemm_fused(int which, const float* __restrict__ U) {
    __shared__ unsigned As[32][128];
    __shared__ unsigned Ws[32][128];
    __shared__ float lut[27];
    __shared__ unsigned char sbits[128][16];   // [row][byte] = 8 col-bits
    __shared__ int icol[128][17];              // [col][ty] partial colsums

    const unsigned* __restrict__ Wb = (which == 0) ? g_w2 : g_w3;
    int bn0 = blockIdx.x * 128;
    int bm0 = blockIdx.y * 128;
    int tid = threadIdx.x;
    int ty = tid >> 4, tx = tid & 15;

    if (tid < 27) lut[tid] = g_lutf[tid];

#pragma unroll
    for (int i = 0; i < 4; i++) {
        int p = tid * 4 + i;
        int r = p >> 3, c4 = (p & 7) << 2;
        uint4 av = *(const uint4*)&g_act[(size_t)(bm0 + r) * NW + c4];
        As[c4 + 0][r] = av.x; As[c4 + 1][r] = av.y;
        As[c4 + 2][r] = av.z; As[c4 + 3][r] = av.w;
        uint4 wv = *(const uint4*)&Wb[(size_t)(bn0 + r) * NW + c4];
        Ws[c4 + 0][r] = wv.x; Ws[c4 + 1][r] = wv.y;
        Ws[c4 + 2][r] = wv.z; Ws[c4 + 3][r] = wv.w;
    }
    __syncthreads();

    int acc[8][8];
#pragma unroll
    for (int i = 0; i < 8; i++)
#pragma unroll
        for (int j = 0; j < 8; j++) acc[i][j] = 0;

    for (int w = 0; w < 32; w++) {
        unsigned a[8], b[8];
#pragma unroll
        for (int i = 0; i < 8; i++) a[i] = As[w][ty * 8 + i];
#pragma unroll
        for (int j = 0; j < 8; j++) b[j] = Ws[w][tx * 8 + j];
#pragma unroll
        for (int i = 0; i < 8; i++)
#pragma unroll
            for (int j = 0; j < 8; j++) acc[i][j] += __popc(a[i] ^ b[j]);
    }

    int csum[8];
#pragma unroll
    for (int j = 0; j < 8; j++) csum[j] = 0;
#pragma unroll
    for (int i = 0; i < 8; i++) {
        int rowg = bm0 + ty * 8 + i;
        float4 u0 = *(const float4*)&U[(size_t)rowg * HH + bn0 + tx * 8];
        float4 u1 = *(const float4*)&U[(size_t)rowg * HH + bn0 + tx * 8 + 4];
        float uu[8] = {u0.x, u0.y, u0.z, u0.w, u1.x, u1.y, u1.z, u1.w};
        unsigned byte = 0;
#pragma unroll
        for (int j = 0; j < 8; j++) {
            int cnt = acc[i][j];
            int hs = 512 - cnt;                 // h/2
            int m = (hs < 0) ? -hs : hs;
            if (m > 26) m = 26;
            bool pos = (hs > 0) ^ (uu[j] < lut[m]);
            byte |= (pos ? 1u : 0u) << j;
            csum[j] += pos ? 1 : -1;
        }
        sbits[ty * 8 + i][tx] = (unsigned char)byte;
    }
#pragma unroll
    for (int j = 0; j < 8; j++) icol[tx * 8 + j][ty] = csum[j];
    __syncthreads();

#pragma unroll
    for (int v = 0; v < 2; v++) {
        int wi = tid * 2 + v;
        int row = wi >> 2, w = wi & 3;
        unsigned word = *(const unsigned*)&sbits[row][w * 4];
        g_nv[(size_t)(bm0 + row) * NW + blockIdx.x * 4 + w] = word;
    }
    if (tid < 128) {
        int s = 0;
#pragma unroll
        for (int t = 0; t < 16; t++) s += icol[tid][t];
        g_part[blockIdx.y][bn0 + tid] = (double)s;
    }
}

// Per-column BN+sign LUT masks: out_bit = (nv_bit & sel) ^ mb.
__global__ void k_lut(const float* __restrict__ gv, const float* __restrict__ bv) {
    int c = threadIdx.x;        // 1024 threads
    double s = 0;
    for (int p = 0; p < NPART; p++) s += g_part[p][c];
    double mu = s / (double)BB;
    double r = 1.0 / sqrt(1.0 - mu * mu + 1e-5);
    double zp = (( 1.0 - mu) * r) * (double)gv[c] + (double)bv[c];
    double zm = ((-1.0 - mu) * r) * (double)gv[c] + (double)bv[c];
    unsigned pb = __ballot_sync(0xffffffffu, zp > 0.0);
    unsigned mb = __ballot_sync(0xffffffffu, zm > 0.0);
    if ((c & 31) == 0) {
        g_sel[c >> 5] = pb ^ mb;
        g_mb[c >> 5]  = mb;
    }
}

__global__ void k_apply() {
    int i = blockIdx.x * 256 + threadIdx.x;
    int w = i & (NW - 1);
    g_act[i] = (g_nv[i] & g_sel[w]) ^ g_mb[w];
}

// Output layer
__global__ __launch_bounds__(256) void k_out(float* __restrict__ outp) {
    __shared__ unsigned As[256][33];
    __shared__ unsigned W4s[NOUT][NW];
    int r0 = blockIdx.x * 256;
    int t = threadIdx.x;
#pragma unroll
    for (int i = 0; i < 32; i++) {
        int p = t + 256 * i;
        As[p >> 5][p & 31] = g_act[(size_t)r0 * NW + p];
    }
    for (int i = t; i < NOUT * NW; i += 256) ((unsigned*)W4s)[i] = g_w4[i];
    __syncthreads();
#pragma unroll
    for (int o = 0; o < NOUT; o++) {
        int cnt = 0;
#pragma unroll
        for (int w = 0; w < NW; w++) cnt += __popc(As[t][w] ^ W4s[o][w]);
        outp[(size_t)(r0 + t) * NOUT + o] = (float)(HH - 2 * cnt);
    }
}

// ===================================================================
extern "C" void kernel_launch(void* const* d_in, const int* in_sizes, int n_in,
                              void* d_out, int out_size) {
    const float* x  = (const float*)d_in[0];
    const float* u2 = (const float*)d_in[1];
    const float* u3 = (const float*)d_in[2];
    const float* W1 = (const float*)d_in[3];
    const float* W2 = (const float*)d_in[4];
    const float* W3 = (const float*)d_in[5];
    const float* W4 = (const float*)d_in[6];
    const float* g1 = (const float*)d_in[7];
    const float* b1 = (const float*)d_in[8];
    const float* g2 = (const float*)d_in[9];
    const float* b2 = (const float*)d_in[10];
    const float* g3 = (const float*)d_in[11];
    const float* b3 = (const float*)d_in[12];
    float* out = (float*)d_out;

    k_mklut<<<1, 27>>>();
    {
        dim3 tb(32, 8), tg((K1 + 31) / 32, HH / 32);
        k_signW1<<<tg, tb>>>(W1);
    }
    k_packAll<<<(2 * W2_ELEMS + W4_ELEMS + 255) / 256, 256>>>(W2, W3, W4);

    dim3 ggrid(HH / 128, BB / 128);

    // Layer 1 (GEMM + fused BN stats)
    k_gemm1<<<ggrid, 256>>>(x);
    k_reduce1<<<HH / 256, 256>>>();
    k_pack1<<<(BB * HH) / 256, 256>>>(g1, b1);

    // Layer 2
    k_bgemm_fused<<<ggrid, 256>>>(0, u2);
    k_lut<<<1, HH>>>(g2, b2);
    k_apply<<<(BB * NW) / 256, 256>>>();

    // Layer 3
    k_bgemm_fused<<<ggrid, 256>>>(1, u3);
    k_lut<<<1, HH>>>(g3, b3);
    k_apply<<<(BB * NW) / 256, 256>>>();

    // Output layer
    k_out<<<BB / 256, 256>>>(out);
}

// round 9
// speedup vs baseline: 1.8550x; 1.0442x over previous
#include <cuda_runtime.h>
#include <cstdint>
#include <math.h>

// ===== Problem dims =====
#define BB   16384
#define K1   784
#define HH   1024
#define NW   32          // HH/32 packed words per row
#define NOUT 10
#define NPART 128        // bgemm partial blocks (grid.y = BB/128)
#define NPART1 64        // gemm1 partial blocks (grid.y = BB/256)

// ===== Scratch (device globals) =====
__device__ float    g_h[(size_t)BB*HH];
__device__ unsigned g_nv[BB*NW];
__device__ unsigned g_act[BB*NW];
__device__ float    g_sW1[K1*HH];           // sign(W1)^T, [k][n]
__device__ unsigned g_w2[HH*NW];
__device__ unsigned g_w3[HH*NW];
__device__ unsigned g_w4[NOUT*NW];
__device__ double   g_part[NPART][2*HH];
__device__ float    g_muf[HH];
__device__ float    g_rf[HH];
__device__ unsigned g_sel[NW];
__device__ unsigned g_mb[NW];
__device__ float    g_lutf[27];

// packed f32x2 fma: halves round independently (rn) -> each half's chain
// is bit-identical to scalar FFMA in the same order.
__device__ __forceinline__ unsigned long long fma2(unsigned long long a,
                                                   unsigned long long b,
                                                   unsigned long long c) {
    unsigned long long d;
    asm("fma.rn.f32x2 %0, %1, %2, %3;" : "=l"(d) : "l"(a), "l"(b), "l"(c));
    return d;
}
__device__ __forceinline__ unsigned long long dup2(float a) {
    unsigned long long d;
    asm("mov.b64 %0, {%1, %1};" : "=l"(d) : "r"(__float_as_uint(a)));
    return d;
}
__device__ __forceinline__ void kadd(float v, float& s, float& c) {
    float y = __fsub_rn(v, c);
    float t = __fadd_rn(s, y);
    c = __fsub_rn(__fsub_rn(t, s), y);
    s = t;
}

// ===================================================================
// Flip-threshold LUT (exact vs fp64 path; see R4 derivation)
// ===================================================================
__global__ void k_mklut() {
    int m = threadIdx.x;          // 0..26
    float t;
    if (m <= 25) {
        float x = (float)(2 * m);
        float q2 = (x * x) / 50.0f;
        double prob = 0.5 * exp(-(double)q2);
        t = (float)prob;
        if ((double)t < prob) t = __int_as_float(__float_as_int(t) + 1);
    } else t = -1.0f;
    g_lutf[m] = t;
}

// sign(W1)^T via smem tile transpose
__global__ void k_signW1(const float* __restrict__ W1) {
    __shared__ float tile[32][33];
    int k0 = blockIdx.x * 32, n0 = blockIdx.y * 32;
    int tx = threadIdx.x, ty = threadIdx.y;      // (32, 8)
#pragma unroll
    for (int r = 0; r < 32; r += 8) {
        int n = n0 + ty + r, k = k0 + tx;
        float w = (k < K1) ? W1[(size_t)n * K1 + k] : 0.f;
        tile[ty + r][tx] = (w > 0.f) ? 1.f : ((w < 0.f) ? -1.f : 0.f);
    }
    __syncthreads();
#pragma unroll
    for (int r = 0; r < 32; r += 8) {
        int k = k0 + ty + r, n = n0 + tx;
        if (k < K1) g_sW1[(size_t)k * HH + n] = tile[tx][ty + r];
    }
}

// Single kernel packs W2, W3, W4 sign bits
#define W2_ELEMS (HH*HH)
#define W4_ELEMS (NOUT*HH)
__global__ void k_packAll(const float* __restrict__ W2,
                          const float* __restrict__ W3,
                          const float* __restrict__ W4) {
    int idx = blockIdx.x * 256 + threadIdx.x;
    const float* W; unsigned* dst; int off;
    if (idx < W2_ELEMS)               { W = W2; dst = g_w2; off = 0; }
    else if (idx < 2 * W2_ELEMS)      { W = W3; dst = g_w3; off = W2_ELEMS; }
    else                              { W = W4; dst = g_w4; off = 2 * W2_ELEMS; }
    int li = idx - off;
    bool pos = (idx < 2 * W2_ELEMS + W4_ELEMS) ? (W[li] > 0.f) : false;
    unsigned bal = __ballot_sync(0xffffffffu, pos);
    if ((threadIdx.x & 31) == 0 && idx < 2 * W2_ELEMS + W4_ELEMS) dst[li >> 5] = bal;
}

// ===================================================================
// Layer 1 SGEMM: 256x128 CTA tile, 16x8 per thread, BK=16, double-buffered
// f32x2. L1-crossbar relief: A reads broadcast across 16 tx lanes; unique
// smem bytes/FMA cut ~44% vs 128x128/8x8. Per-output chain: one accumulator,
// k ascending -> bit-identical to reference. Fused BN1 stats epilogue.
// ===================================================================
__global__ __launch_bounds__(256, 1) void k_gemm1(const float* __restrict__ X) {
    __shared__ union {
        struct { float As[2][16][256]; float Bs[2][16][128]; } g;   // 48 KB
        struct { float s[16][128]; float c[16][128];
                 float q[16][128]; float cq[16][128]; } st;         // 32 KB
    } sm;
    int bn0 = blockIdx.x * 128;
    int bm0 = blockIdx.y * 256;
    int tid = threadIdx.x;
    int ty = tid >> 4, tx = tid & 15;

    // A loader: each thread owns global row (bm0+tid), loads 16 k-floats/tile
    const float* aptr = &X[(size_t)(bm0 + tid) * K1];
    // B loader: row ty of the k-tile, cols tx*8 .. tx*8+7 (two float4s)
    const float* bptr = &g_sW1[(size_t)ty * HH + bn0 + tx * 8];

    unsigned long long acc2[16][4];
#pragma unroll
    for (int i = 0; i < 16; i++)
#pragma unroll
        for (int q = 0; q < 4; q++) acc2[i][q] = 0ULL;

    float4 av[4], bv0, bv1;
#pragma unroll
    for (int i = 0; i < 4; i++) av[i] = *(const float4*)(aptr + 4 * i);
    bv0 = *(const float4*)bptr;
    bv1 = *(const float4*)(bptr + 4);
    {
#pragma unroll
        for (int i = 0; i < 4; i++) {
            sm.g.As[0][4*i + 0][tid] = av[i].x;
            sm.g.As[0][4*i + 1][tid] = av[i].y;
            sm.g.As[0][4*i + 2][tid] = av[i].z;
            sm.g.As[0][4*i + 3][tid] = av[i].w;
        }
        *(float4*)&sm.g.Bs[0][ty][tx * 8]     = bv0;
        *(float4*)&sm.g.Bs[0][ty][tx * 8 + 4] = bv1;
    }
    __syncthreads();

    int buf = 0;
    for (int kt = 16; kt <= K1; kt += 16) {
        bool more = (kt < K1);
        if (more) {
#pragma unroll
            for (int i = 0; i < 4; i++) av[i] = *(const float4*)(aptr + kt + 4 * i);
            bv0 = *(const float4*)(bptr + (size_t)kt * HH);
            bv1 = *(const float4*)(bptr + (size_t)kt * HH + 4);
        }
#pragma unroll
        for (int k = 0; k < 16; k++) {
            float4 a0 = *(const float4*)&sm.g.As[buf][k][ty * 16];
            float4 a1 = *(const float4*)&sm.g.As[buf][k][ty * 16 + 4];
            float4 a2 = *(const float4*)&sm.g.As[buf][k][ty * 16 + 8];
            float4 a3 = *(const float4*)&sm.g.As[buf][k][ty * 16 + 12];
            ulonglong2 b01 = *(const ulonglong2*)&sm.g.Bs[buf][k][tx * 8];
            ulonglong2 b23 = *(const ulonglong2*)&sm.g.Bs[buf][k][tx * 8 + 4];
            unsigned long long bq[4] = {b01.x, b01.y, b23.x, b23.y};
            float a[16] = {a0.x, a0.y, a0.z, a0.w, a1.x, a1.y, a1.z, a1.w,
                           a2.x, a2.y, a2.z, a2.w, a3.x, a3.y, a3.z, a3.w};
#pragma unroll
            for (int i = 0; i < 16; i++) {
                unsigned long long ai = dup2(a[i]);
#pragma unroll
                for (int q = 0; q < 4; q++)
                    acc2[i][q] = fma2(ai, bq[q], acc2[i][q]);
            }
        }
        if (more) {
            int nb = buf ^ 1;
#pragma unroll
            for (int i = 0; i < 4; i++) {
                sm.g.As[nb][4*i + 0][tid] = av[i].x;
                sm.g.As[nb][4*i + 1][tid] = av[i].y;
                sm.g.As[nb][4*i + 2][tid] = av[i].z;
                sm.g.As[nb][4*i + 3][tid] = av[i].w;
            }
            *(float4*)&sm.g.Bs[nb][ty][tx * 8]     = bv0;
            *(float4*)&sm.g.Bs[nb][ty][tx * 8 + 4] = bv1;
            __syncthreads();
            buf = nb;
        }
    }

    // Store h + per-thread Kahan column stats (16 rows each, ascending i)
    float ss[8] = {0,0,0,0,0,0,0,0}, sc[8] = {0,0,0,0,0,0,0,0};
    float qs[8] = {0,0,0,0,0,0,0,0}, qc[8] = {0,0,0,0,0,0,0,0};
#pragma unroll
    for (int i = 0; i < 16; i++) {
        unsigned long long* p =
            (unsigned long long*)&g_h[(size_t)(bm0 + ty * 16 + i) * HH + bn0 + tx * 8];
        *(ulonglong2*)p       = make_ulonglong2(acc2[i][0], acc2[i][1]);
        *(ulonglong2*)(p + 2) = make_ulonglong2(acc2[i][2], acc2[i][3]);
#pragma unroll
        for (int q = 0; q < 4; q++) {
            float2 v2 = *(float2*)&acc2[i][q];
            kadd(v2.x, ss[2*q],   sc[2*q]);
            kadd(__fmul_rn(v2.x, v2.x), qs[2*q],   qc[2*q]);
            kadd(v2.y, ss[2*q+1], sc[2*q+1]);
            kadd(__fmul_rn(v2.y, v2.y), qs[2*q+1], qc[2*q+1]);
        }
    }
    __syncthreads();   // smem reuse safe
#pragma unroll
    for (int j = 0; j < 8; j++) {
        int col = tx * 8 + j;
        sm.st.s[ty][col]  = ss[j];
        sm.st.c[ty][col]  = sc[j];
        sm.st.q[ty][col]  = qs[j];
        sm.st.cq[ty][col] = qc[j];
    }
    __syncthreads();
    if (tid < 128) {
        double sd = 0, qd = 0;
#pragma unroll
        for (int t = 0; t < 16; t++) {
            sd += (double)sm.st.s[t][tid] - (double)sm.st.c[t][tid];
            qd += (double)sm.st.q[t][tid] - (double)sm.st.cq[t][tid];
        }
        g_part[blockIdx.y][bn0 + tid]      = sd;
        g_part[blockIdx.y][HH + bn0 + tid] = qd;
    }
}

__global__ void k_reduce1() {
    int c = blockIdx.x * 256 + threadIdx.x;
    double s = 0, sq = 0;
    for (int p = 0; p < NPART1; p++) { s += g_part[p][c]; sq += g_part[p][HH + c]; }
    double mu = s / (double)BB;
    double var = sq / (double)BB - mu * mu;
    g_muf[c] = (float)mu;
    g_rf[c]  = (float)(1.0 / sqrt(var + 1e-5));
}

__global__ void k_pack1(const float* __restrict__ gv, const float* __restrict__ bv) {
    int idx = blockIdx.x * 256 + threadIdx.x;
    int c = idx & (HH - 1);
    float h = g_h[idx];
    float z = __fadd_rn(__fmul_rn(__fmul_rn(__fsub_rn(h, g_muf[c]), g_rf[c]), gv[c]), bv[c]);
    unsigned bal = __ballot_sync(0xffffffffu, z > 0.f);
    if ((threadIdx.x & 31) == 0) g_act[idx >> 5] = bal;
}

// ===================================================================
// Fused binary GEMM + noisy_binarize + bit-pack + column-sums (exact int)
// ===================================================================
__global__ __launch_bounds__(256) void k_bgemm_fused(int which, const float* __restrict__ U) {
    __shared__ unsigned As[32][128];
    __shared__ unsigned Ws[32][128];
    __shared__ float lut[27];
    __shared__ unsigned char sbits[128][16];
    __shared__ int icol[128][17];

    const unsigned* __restrict__ Wb = (which == 0) ? g_w2 : g_w3;
    int bn0 = blockIdx.x * 128;
    int bm0 = blockIdx.y * 128;
    int tid = threadIdx.x;
    int ty = tid >> 4, tx = tid & 15;

    if (tid < 27) lut[tid] = g_lutf[tid];

#pragma unroll
    for (int i = 0; i < 4; i++) {
        int p = tid * 4 + i;
        int r = p >> 3, c4 = (p & 7) << 2;
        uint4 av = *(const uint4*)&g_act[(size_t)(bm0 + r) * NW + c4];
        As[c4 + 0][r] = av.x; As[c4 + 1][r] = av.y;
        As[c4 + 2][r] = av.z; As[c4 + 3][r] = av.w;
        uint4 wv = *(const uint4*)&Wb[(size_t)(bn0 + r) * NW + c4];
        Ws[c4 + 0][r] = wv.x; Ws[c4 + 1][r] = wv.y;
        Ws[c4 + 2][r] = wv.z; Ws[c4 + 3][r] = wv.w;
    }
    __syncthreads();

    int acc[8][8];
#pragma unroll
    for (int i = 0; i < 8; i++)
#pragma unroll
        for (int j = 0; j < 8; j++) acc[i][j] = 0;

    for (int w = 0; w < 32; w++) {
        unsigned a[8], b[8];
#pragma unroll
        for (int i = 0; i < 8; i++) a[i] = As[w][ty * 8 + i];
#pragma unroll
        for (int j = 0; j < 8; j++) b[j] = Ws[w][tx * 8 + j];
#pragma unroll
        for (int i = 0; i < 8; i++)
#pragma unroll
            for (int j = 0; j < 8; j++) acc[i][j] += __popc(a[i] ^ b[j]);
    }

    int csum[8];
#pragma unroll
    for (int j = 0; j < 8; j++) csum[j] = 0;
#pragma unroll
    for (int i = 0; i < 8; i++) {
        int rowg = bm0 + ty * 8 + i;
        float4 u0 = *(const float4*)&U[(size_t)rowg * HH + bn0 + tx * 8];
        float4 u1 = *(const float4*)&U[(size_t)rowg * HH + bn0 + tx * 8 + 4];
        float uu[8] = {u0.x, u0.y, u0.z, u0.w, u1.x, u1.y, u1.z, u1.w};
        unsigned byte = 0;
#pragma unroll
        for (int j = 0; j < 8; j++) {
            int cnt = acc[i][j];
            int hs = 512 - cnt;                 // h/2
            int m = (hs < 0) ? -hs : hs;
            if (m > 26) m = 26;
            bool pos = (hs > 0) ^ (uu[j] < lut[m]);
            byte |= (pos ? 1u : 0u) << j;
            csum[j] += pos ? 1 : -1;
        }
        sbits[ty * 8 + i][tx] = (unsigned char)byte;
    }
#pragma unroll
    for (int j = 0; j < 8; j++) icol[tx * 8 + j][ty] = csum[j];
    __syncthreads();

#pragma unroll
    for (int v = 0; v < 2; v++) {
        int wi = tid * 2 + v;
        int row = wi >> 2, w = wi & 3;
        unsigned word = *(const unsigned*)&sbits[row][w * 4];
        g_nv[(size_t)(bm0 + row) * NW + blockIdx.x * 4 + w] = word;
    }
    if (tid < 128) {
        int s = 0;
#pragma unroll
        for (int t = 0; t < 16; t++) s += icol[tid][t];
        g_part[blockIdx.y][bn0 + tid] = (double)s;
    }
}

__global__ void k_lut(const float* __restrict__ gv, const float* __restrict__ bv) {
    int c = threadIdx.x;        // 1024 threads
    double s = 0;
    for (int p = 0; p < NPART; p++) s += g_part[p][c];
    double mu = s / (double)BB;
    double r = 1.0 / sqrt(1.0 - mu * mu + 1e-5);
    double zp = (( 1.0 - mu) * r) * (double)gv[c] + (double)bv[c];
    double zm = ((-1.0 - mu) * r) * (double)gv[c] + (double)bv[c];
    unsigned pb = __ballot_sync(0xffffffffu, zp > 0.0);
    unsigned mb = __ballot_sync(0xffffffffu, zm > 0.0);
    if ((c & 31) == 0) {
        g_sel[c >> 5] = pb ^ mb;
        g_mb[c >> 5]  = mb;
    }
}

__global__ void k_apply() {
    int i = blockIdx.x * 256 + threadIdx.x;
    int w = i & (NW - 1);
    g_act[i] = (g_nv[i] & g_sel[w]) ^ g_mb[w];
}

__global__ __launch_bounds__(256) void k_out(float* __restrict__ outp) {
    __shared__ unsigned As[256][33];
    __shared__ unsigned W4s[NOUT][NW];
    int r0 = blockIdx.x * 256;
    int t = threadIdx.x;
#pragma unroll
    for (int i = 0; i < 32; i++) {
        int p = t + 256 * i;
        As[p >> 5][p & 31] = g_act[(size_t)r0 * NW + p];
    }
    for (int i = t; i < NOUT * NW; i += 256) ((unsigned*)W4s)[i] = g_w4[i];
    __syncthreads();
#pragma unroll
    for (int o = 0; o < NOUT; o++) {
        int cnt = 0;
#pragma unroll
        for (int w = 0; w < NW; w++) cnt += __popc(As[t][w] ^ W4s[o][w]);
        outp[(size_t)(r0 + t) * NOUT + o] = (float)(HH - 2 * cnt);
    }
}

// ===================================================================
extern "C" void kernel_launch(void* const* d_in, const int* in_sizes, int n_in,
                              void* d_out, int out_size) {
    const float* x  = (const float*)d_in[0];
    const float* u2 = (const float*)d_in[1];
    const float* u3 = (const float*)d_in[2];
    const float* W1 = (const float*)d_in[3];
    const float* W2 = (const float*)d_in[4];
    const float* W3 = (const float*)d_in[5];
    const float* W4 = (const float*)d_in[6];
    const float* g1 = (const float*)d_in[7];
    const float* b1 = (const float*)d_in[8];
    const float* g2 = (const float*)d_in[9];
    const float* b2 = (const float*)d_in[10];
    const float* g3 = (const float*)d_in[11];
    const float* b3 = (const float*)d_in[12];
    float* out = (float*)d_out;

    k_mklut<<<1, 27>>>();
    {
        dim3 tb(32, 8), tg((K1 + 31) / 32, HH / 32);
        k_signW1<<<tg, tb>>>(W1);
    }
    k_packAll<<<(2 * W2_ELEMS + W4_ELEMS + 255) / 256, 256>>>(W2, W3, W4);

    // Layer 1: 256x128 tiles -> grid (8, 64)
    dim3 g1grid(HH / 128, BB / 256);
    k_gemm1<<<g1grid, 256>>>(x);
    k_reduce1<<<HH / 256, 256>>>();
    k_pack1<<<(BB * HH) / 256, 256>>>(g1, b1);

    dim3 ggrid(HH / 128, BB / 128);
    // Layer 2
    k_bgemm_fused<<<ggrid, 256>>>(0, u2);
    k_lut<<<1, HH>>>(g2, b2);
    k_apply<<<(BB * NW) / 256, 256>>>();

    // Layer 3
    k_bgemm_fused<<<ggrid, 256>>>(1, u3);
    k_lut<<<1, HH>>>(g3, b3);
    k_apply<<<(BB * NW) / 256, 256>>>();

    // Output layer
    k_out<<<BB / 256, 256>>>(out);
}